// round 3
// baseline (speedup 1.0000x reference)
#include <cuda_runtime.h>
#include <cstdint>

// ============================================================================
// out[b,c] = sum_d W[c,d] * (softmax(mod[b,:])[d] + 1) * x[b,d]
// B=8192, D=1024, C=4096, fp32.
//
// Harness PTX target is sm_103 (no 'a') -> tcgen05/TMEM/TMA are unavailable.
// Plan: baseline-PTX tensor cores via mma.sync m16n8k8 tf32 + cp.async.
//   Phase 0: round W to tf32       -> g_w
//   Phase 1: y = (softmax+1)*x, rounded to tf32 -> g_y
//   Phase 2: out = y @ W^T, Ampere-style 4-stage pipelined GEMM, 128x128x32
// ============================================================================

#define Bq 8192
#define Dq 1024
#define Cq 4096

#define BM 128
#define BN 128
#define BK 32
#define NT (Dq / BK)        // 32 k-tiles
#define STAGES 4
#define LDA 36              // BK + 4 pad (floats) -> conflict-free fragment lds
#define TILE_FLOATS (BM * LDA)              // 4608
#define STAGE_FLOATS (2 * TILE_FLOATS)      // 9216
#define SMEM_BYTES (STAGES * STAGE_FLOATS * 4)  // 147456

__device__ float g_y[(size_t)Bq * Dq];
__device__ float g_w[(size_t)Cq * Dq];

__device__ __forceinline__ uint32_t smem_u32(const void* p) {
    uint32_t a;
    asm("{ .reg .u64 t; cvta.to.shared.u64 t, %1; cvt.u32.u64 %0, t; }" : "=r"(a) : "l"(p));
    return a;
}

__device__ __forceinline__ uint32_t to_tf32(float f) {
    uint32_t u;
    asm("cvt.rna.tf32.f32 %0, %1;" : "=r"(u) : "f"(f));
    return u;
}

__device__ __forceinline__ void cp_async16(uint32_t dst, const void* src) {
    asm volatile("cp.async.cg.shared.global [%0], [%1], 16;" :: "r"(dst), "l"(src) : "memory");
}
#define CP_COMMIT() asm volatile("cp.async.commit_group;" ::: "memory")
#define CP_WAIT(n)  asm volatile("cp.async.wait_group %0;" :: "n"(n) : "memory")

__device__ __forceinline__ void mma_tf32(float c[4], uint32_t a0, uint32_t a1,
                                         uint32_t a2, uint32_t a3,
                                         uint32_t b0, uint32_t b1) {
    asm volatile(
        "mma.sync.aligned.m16n8k8.row.col.f32.tf32.tf32.f32 "
        "{%0,%1,%2,%3}, {%4,%5,%6,%7}, {%8,%9}, {%0,%1,%2,%3};"
        : "+f"(c[0]), "+f"(c[1]), "+f"(c[2]), "+f"(c[3])
        : "r"(a0), "r"(a1), "r"(a2), "r"(a3), "r"(b0), "r"(b1));
}

// ---------------------------------------------------------------------------
// Phase 0: W -> tf32-rounded copy
// ---------------------------------------------------------------------------
__global__ __launch_bounds__(256) void cvt_w_kernel(const float* __restrict__ W,
                                                    float* __restrict__ Wt)
{
    size_t i = (size_t)blockIdx.x * 256 + threadIdx.x;
    float4 v = reinterpret_cast<const float4*>(W)[i];
    uint4 o;
    o.x = to_tf32(v.x); o.y = to_tf32(v.y); o.z = to_tf32(v.z); o.w = to_tf32(v.w);
    reinterpret_cast<uint4*>(Wt)[i] = o;
}

// ---------------------------------------------------------------------------
// Phase 1: y[b,d] = (softmax(mod[b,:])[d] + 1) * x[b,d], tf32-rounded
// One CTA per row, 256 threads, float4 per thread (D=1024).
// ---------------------------------------------------------------------------
__global__ __launch_bounds__(256) void softmax_scale_kernel(
    const float* __restrict__ x, const float* __restrict__ mod, float* __restrict__ y)
{
    int b = blockIdx.x;
    int t = threadIdx.x;
    const float4 m4 = reinterpret_cast<const float4*>(mod + (size_t)b * Dq)[t];
    const float4 x4 = reinterpret_cast<const float4*>(x + (size_t)b * Dq)[t];

    float mx = fmaxf(fmaxf(m4.x, m4.y), fmaxf(m4.z, m4.w));
    #pragma unroll
    for (int o = 16; o; o >>= 1) mx = fmaxf(mx, __shfl_xor_sync(0xffffffffu, mx, o));

    __shared__ float sred[8];
    int w = t >> 5, l = t & 31;
    if (l == 0) sred[w] = mx;
    __syncthreads();
    float gmx = sred[0];
    #pragma unroll
    for (int i = 1; i < 8; i++) gmx = fmaxf(gmx, sred[i]);
    __syncthreads();

    float e0 = expf(m4.x - gmx), e1 = expf(m4.y - gmx);
    float e2 = expf(m4.z - gmx), e3 = expf(m4.w - gmx);
    float s = e0 + e1 + e2 + e3;
    #pragma unroll
    for (int o = 16; o; o >>= 1) s += __shfl_xor_sync(0xffffffffu, s, o);
    if (l == 0) sred[w] = s;
    __syncthreads();
    float tot = 0.0f;
    #pragma unroll
    for (int i = 0; i < 8; i++) tot += sred[i];
    float inv = 1.0f / tot;

    uint4 o4;
    o4.x = to_tf32(fmaf(e0, inv, 1.0f) * x4.x);
    o4.y = to_tf32(fmaf(e1, inv, 1.0f) * x4.y);
    o4.z = to_tf32(fmaf(e2, inv, 1.0f) * x4.z);
    o4.w = to_tf32(fmaf(e3, inv, 1.0f) * x4.w);
    reinterpret_cast<uint4*>(y + (size_t)b * Dq)[t] = o4;
}

// ---------------------------------------------------------------------------
// Phase 2: out = y @ W^T. 128x128x32 tiles, 256 thr (8 warps as 2x4),
// 4-stage cp.async pipeline, mma.sync m16n8k8 tf32.
// Warp tile 64x32: 4 m-tiles (16) x 4 n-tiles (8), 64 accum regs.
// ---------------------------------------------------------------------------
__global__ __launch_bounds__(256) void gemm_tf32_kernel(
    const float* __restrict__ A,   // g_y  [B][D]
    const float* __restrict__ Bw,  // g_w  [C][D]
    float* __restrict__ out)       // [B][C]
{
    extern __shared__ float smem[];
    const uint32_t sbase = smem_u32(smem);
    const int tid  = threadIdx.x;
    const int wid  = tid >> 5;
    const int lane = tid & 31;
    const int m0 = blockIdx.y * BM;
    const int n0 = blockIdx.x * BN;
    const int warp_m = wid >> 2;   // 0..1 -> 64-row half
    const int warp_n = wid & 3;    // 0..3 -> 32-col quarter

    // --- async tile loader: A rows m0.., B rows n0.., k0 = kt*BK ---
    const int ldrow = tid >> 3;    // 0..31
    const int ldch  = tid & 7;     // 16B chunk within 128B row
    auto load_tile = [&](int s, int kt) {
        const int k0 = kt * BK;
        const uint32_t sA = sbase + (uint32_t)(s * STAGE_FLOATS) * 4u;
        const uint32_t sB = sA + TILE_FLOATS * 4u;
        #pragma unroll
        for (int i = 0; i < 4; i++) {
            int r = ldrow + 32 * i;
            cp_async16(sA + (uint32_t)(r * LDA + ldch * 4) * 4u,
                       A + (size_t)(m0 + r) * Dq + k0 + ldch * 4);
            cp_async16(sB + (uint32_t)(r * LDA + ldch * 4) * 4u,
                       Bw + (size_t)(n0 + r) * Dq + k0 + ldch * 4);
        }
    };

    float acc[4][4][4];
    #pragma unroll
    for (int mt = 0; mt < 4; mt++)
        #pragma unroll
        for (int nt = 0; nt < 4; nt++)
            #pragma unroll
            for (int i = 0; i < 4; i++) acc[mt][nt][i] = 0.0f;

    int fetch = 0;
    #pragma unroll
    for (; fetch < STAGES - 1; fetch++) { load_tile(fetch, fetch); CP_COMMIT(); }
    CP_WAIT(STAGES - 2);
    __syncthreads();

    const int fr = lane >> 2;      // fragment row / n-group
    const int fc = lane & 3;       // fragment k within quad

    for (int kt = 0; kt < NT; kt++) {
        const int cur = kt % STAGES;
        if (fetch < NT) { load_tile(fetch % STAGES, fetch); fetch++; }
        CP_COMMIT();

        const float* sA = smem + cur * STAGE_FLOATS;
        const float* sB = sA + TILE_FLOATS;

        #pragma unroll
        for (int ks = 0; ks < 4; ks++) {
            const int kc = ks * 8 + fc;
            uint32_t af[4][4], bf[4][2];
            #pragma unroll
            for (int mt = 0; mt < 4; mt++) {
                int row = warp_m * 64 + mt * 16 + fr;
                af[mt][0] = __float_as_uint(sA[row * LDA + kc]);
                af[mt][1] = __float_as_uint(sA[(row + 8) * LDA + kc]);
                af[mt][2] = __float_as_uint(sA[row * LDA + kc + 4]);
                af[mt][3] = __float_as_uint(sA[(row + 8) * LDA + kc + 4]);
            }
            #pragma unroll
            for (int nt = 0; nt < 4; nt++) {
                int nrow = warp_n * 32 + nt * 8 + fr;
                bf[nt][0] = __float_as_uint(sB[nrow * LDA + kc]);
                bf[nt][1] = __float_as_uint(sB[nrow * LDA + kc + 4]);
            }
            #pragma unroll
            for (int mt = 0; mt < 4; mt++)
                #pragma unroll
                for (int nt = 0; nt < 4; nt++)
                    mma_tf32(acc[mt][nt], af[mt][0], af[mt][1], af[mt][2], af[mt][3],
                             bf[nt][0], bf[nt][1]);
        }
        CP_WAIT(STAGES - 2);
        __syncthreads();
    }

    // --- epilogue: direct float2 stores ---
    #pragma unroll
    for (int mt = 0; mt < 4; mt++) {
        int rg = m0 + warp_m * 64 + mt * 16 + fr;
        #pragma unroll
        for (int nt = 0; nt < 4; nt++) {
            int cg = n0 + warp_n * 32 + nt * 8 + fc * 2;
            float2* p0 = reinterpret_cast<float2*>(out + (size_t)rg * Cq + cg);
            float2* p1 = reinterpret_cast<float2*>(out + (size_t)(rg + 8) * Cq + cg);
            *p0 = make_float2(acc[mt][nt][0], acc[mt][nt][1]);
            *p1 = make_float2(acc[mt][nt][2], acc[mt][nt][3]);
        }
    }
}

// ---------------------------------------------------------------------------
// Host launcher
// ---------------------------------------------------------------------------
extern "C" void kernel_launch(void* const* d_in, const int* in_sizes, int n_in,
                              void* d_out, int out_size)
{
    const float* x   = (const float*)d_in[0];
    const float* mod = (const float*)d_in[1];
    const float* W   = (const float*)d_in[2];
    float* out = (float*)d_out;

    float* yptr = nullptr;
    float* wptr = nullptr;
    cudaGetSymbolAddress((void**)&yptr, g_y);
    cudaGetSymbolAddress((void**)&wptr, g_w);

    cvt_w_kernel<<<(Cq * Dq / 4) / 256, 256>>>(W, wptr);
    softmax_scale_kernel<<<Bq, 256>>>(x, mod, yptr);

    cudaFuncSetAttribute(gemm_tf32_kernel,
                         cudaFuncAttributeMaxDynamicSharedMemorySize, SMEM_BYTES);
    dim3 grid(Cq / BN, Bq / BM);   // (32, 64)
    gemm_tf32_kernel<<<grid, 256, SMEM_BYTES>>>(yptr, wptr, out);
}

// round 4
// speedup vs baseline: 1.0949x; 1.0949x over previous
#include <cuda_runtime.h>
#include <cstdint>

// ============================================================================
// out[b,c] = sum_d W[c,d] * (softmax(mod[b,:])[d] + 1) * x[b,d]
// B=8192, D=1024, C=4096, fp32.
// sm_103 baseline PTX only (no tcgen05/TMA). mma.sync m16n8k8 tf32 + cp.async
// + ldmatrix.x4 fragment loads.
//   Phase 0: W -> tf32 (g_w)
//   Phase 1: y = (softmax+1)*x -> tf32 (g_y)
//   Phase 2: out = y @ W^T, 128x256 CTA tile, 8 warps (64x64 each), 4 stages
// ============================================================================

#define Bq 8192
#define Dq 1024
#define Cq 4096

#define BM 128
#define BN 256
#define BK 32
#define NT (Dq / BK)        // 32 k-tiles
#define STAGES 4
#define LDA 36              // BK + 4 pad floats: conflict-free ldmatrix + lds

#define A_TILE_FLOATS (BM * LDA)            // 4608
#define B_TILE_FLOATS (BN * LDA)            // 9216
#define STAGE_FLOATS (A_TILE_FLOATS + B_TILE_FLOATS)
#define STAGE_BYTES (STAGE_FLOATS * 4)      // 55296
#define SMEM_BYTES (STAGES * STAGE_BYTES)   // 221184

__device__ float g_y[(size_t)Bq * Dq];
__device__ float g_w[(size_t)Cq * Dq];

__device__ __forceinline__ uint32_t smem_u32(const void* p) {
    uint32_t a;
    asm("{ .reg .u64 t; cvta.to.shared.u64 t, %1; cvt.u32.u64 %0, t; }" : "=r"(a) : "l"(p));
    return a;
}

__device__ __forceinline__ uint32_t to_tf32(float f) {
    uint32_t u;
    asm("cvt.rna.tf32.f32 %0, %1;" : "=r"(u) : "f"(f));
    return u;
}

__device__ __forceinline__ void cp_async16(uint32_t dst, const void* src) {
    asm volatile("cp.async.cg.shared.global [%0], [%1], 16;" :: "r"(dst), "l"(src) : "memory");
}
#define CP_COMMIT() asm volatile("cp.async.commit_group;" ::: "memory")
#define CP_WAIT(n)  asm volatile("cp.async.wait_group %0;" :: "n"(n) : "memory")

#define LDM_X4(r0, r1, r2, r3, addr) \
    asm volatile("ldmatrix.sync.aligned.m8n8.x4.shared.b16 {%0,%1,%2,%3}, [%4];" \
                 : "=r"(r0), "=r"(r1), "=r"(r2), "=r"(r3) : "r"(addr))

__device__ __forceinline__ void mma_tf32(float c[4], uint32_t a0, uint32_t a1,
                                         uint32_t a2, uint32_t a3,
                                         uint32_t b0, uint32_t b1) {
    asm volatile(
        "mma.sync.aligned.m16n8k8.row.col.f32.tf32.tf32.f32 "
        "{%0,%1,%2,%3}, {%4,%5,%6,%7}, {%8,%9}, {%0,%1,%2,%3};"
        : "+f"(c[0]), "+f"(c[1]), "+f"(c[2]), "+f"(c[3])
        : "r"(a0), "r"(a1), "r"(a2), "r"(a3), "r"(b0), "r"(b1));
}

// ---------------------------------------------------------------------------
// Phase 0: W -> tf32-rounded copy
// ---------------------------------------------------------------------------
__global__ __launch_bounds__(256) void cvt_w_kernel(const float* __restrict__ W,
                                                    float* __restrict__ Wt)
{
    size_t i = (size_t)blockIdx.x * 256 + threadIdx.x;
    float4 v = reinterpret_cast<const float4*>(W)[i];
    uint4 o;
    o.x = to_tf32(v.x); o.y = to_tf32(v.y); o.z = to_tf32(v.z); o.w = to_tf32(v.w);
    reinterpret_cast<uint4*>(Wt)[i] = o;
}

// ---------------------------------------------------------------------------
// Phase 1: y[b,d] = (softmax(mod[b,:])[d] + 1) * x[b,d], tf32-rounded
// ---------------------------------------------------------------------------
__global__ __launch_bounds__(256) void softmax_scale_kernel(
    const float* __restrict__ x, const float* __restrict__ mod, float* __restrict__ y)
{
    int b = blockIdx.x;
    int t = threadIdx.x;
    const float4 m4 = reinterpret_cast<const float4*>(mod + (size_t)b * Dq)[t];
    const float4 x4 = reinterpret_cast<const float4*>(x + (size_t)b * Dq)[t];

    float mx = fmaxf(fmaxf(m4.x, m4.y), fmaxf(m4.z, m4.w));
    #pragma unroll
    for (int o = 16; o; o >>= 1) mx = fmaxf(mx, __shfl_xor_sync(0xffffffffu, mx, o));

    __shared__ float sred[8];
    int w = t >> 5, l = t & 31;
    if (l == 0) sred[w] = mx;
    __syncthreads();
    float gmx = sred[0];
    #pragma unroll
    for (int i = 1; i < 8; i++) gmx = fmaxf(gmx, sred[i]);
    __syncthreads();

    float e0 = expf(m4.x - gmx), e1 = expf(m4.y - gmx);
    float e2 = expf(m4.z - gmx), e3 = expf(m4.w - gmx);
    float s = e0 + e1 + e2 + e3;
    #pragma unroll
    for (int o = 16; o; o >>= 1) s += __shfl_xor_sync(0xffffffffu, s, o);
    if (l == 0) sred[w] = s;
    __syncthreads();
    float tot = 0.0f;
    #pragma unroll
    for (int i = 0; i < 8; i++) tot += sred[i];
    float inv = 1.0f / tot;

    uint4 o4;
    o4.x = to_tf32(fmaf(e0, inv, 1.0f) * x4.x);
    o4.y = to_tf32(fmaf(e1, inv, 1.0f) * x4.y);
    o4.z = to_tf32(fmaf(e2, inv, 1.0f) * x4.z);
    o4.w = to_tf32(fmaf(e3, inv, 1.0f) * x4.w);
    reinterpret_cast<uint4*>(y + (size_t)b * Dq)[t] = o4;
}

// ---------------------------------------------------------------------------
// Phase 2: out = y @ W^T. CTA tile 128(M) x 256(N) x 32(K), 256 threads,
// 8 warps in 2(m) x 4(n); warp tile 64x64. ldmatrix.x4 fragment loads.
// ---------------------------------------------------------------------------
__global__ __launch_bounds__(256, 1) void gemm_tf32_kernel(
    const float* __restrict__ A,   // g_y  [B][D]
    const float* __restrict__ Bw,  // g_w  [C][D]
    float* __restrict__ out)       // [B][C]
{
    extern __shared__ float smem[];
    const uint32_t sbase = smem_u32(smem);
    const int tid  = threadIdx.x;
    const int wid  = tid >> 5;
    const int lane = tid & 31;
    const int m0 = blockIdx.y * BM;
    const int n0 = blockIdx.x * BN;
    const int warp_m = wid >> 2;   // 0..1 -> 64-row half of M
    const int warp_n = wid & 3;    // 0..3 -> 64-col quarter of N

    // --- async tile loader ---
    const int ldrow = tid >> 3;    // 0..31
    const int ldch  = (tid & 7) * 4; // float offset of 16B chunk
    auto load_tile = [&](int s, int kt) {
        const int k0 = kt * BK;
        const uint32_t sA = sbase + (uint32_t)(s * STAGE_BYTES);
        const uint32_t sB = sA + A_TILE_FLOATS * 4u;
        #pragma unroll
        for (int i = 0; i < 4; i++) {
            int r = ldrow + 32 * i;
            cp_async16(sA + (uint32_t)(r * LDA + ldch) * 4u,
                       A + (size_t)(m0 + r) * Dq + k0 + ldch);
        }
        #pragma unroll
        for (int i = 0; i < 8; i++) {
            int r = ldrow + 32 * i;
            cp_async16(sB + (uint32_t)(r * LDA + ldch) * 4u,
                       Bw + (size_t)(n0 + r) * Dq + k0 + ldch);
        }
    };

    float acc[4][8][4];
    #pragma unroll
    for (int mt = 0; mt < 4; mt++)
        #pragma unroll
        for (int nt = 0; nt < 8; nt++)
            #pragma unroll
            for (int i = 0; i < 4; i++) acc[mt][nt][i] = 0.0f;

    int fetch = 0;
    #pragma unroll
    for (; fetch < STAGES - 1; fetch++) { load_tile(fetch, fetch); CP_COMMIT(); }
    CP_WAIT(STAGES - 2);
    __syncthreads();

    // ldmatrix per-lane row/khalf: lanes 0-7 rows 0-7 k0, 8-15 rows 8-15 k0,
    // 16-23 rows 0-7 k4, 24-31 rows 8-15 k4
    const int lrow  = lane & 15;
    const int khalf = (lane >> 4) * 4;
    // per-thread invariant float offsets within a tile
    const uint32_t offA0 = (uint32_t)((warp_m * 64 + lrow) * LDA + khalf);
    const uint32_t offB0 = (uint32_t)((warp_n * 64 + lrow) * LDA + khalf);

    const int fr = lane >> 2;      // c-frag row within group
    const int fc = lane & 3;       // c-frag col pair

    for (int kt = 0; kt < NT; kt++) {
        const int cur = kt % STAGES;
        if (fetch < NT) { load_tile(fetch % STAGES, fetch); fetch++; }
        CP_COMMIT();

        const uint32_t sA = sbase + (uint32_t)(cur * STAGE_BYTES);
        const uint32_t sB = sA + A_TILE_FLOATS * 4u;

        #pragma unroll
        for (int ks = 0; ks < 4; ks++) {
            uint32_t af[4][4];
            uint32_t bf[8][2];
            #pragma unroll
            for (int mt = 0; mt < 4; mt++) {
                uint32_t addr = sA + (offA0 + (uint32_t)(mt * 16 * LDA + ks * 8)) * 4u;
                LDM_X4(af[mt][0], af[mt][1], af[mt][2], af[mt][3], addr);
            }
            #pragma unroll
            for (int np = 0; np < 4; np++) {   // each covers nt = 2*np, 2*np+1
                uint32_t addr = sB + (offB0 + (uint32_t)(np * 16 * LDA + ks * 8)) * 4u;
                LDM_X4(bf[2 * np][0], bf[2 * np + 1][0],
                       bf[2 * np][1], bf[2 * np + 1][1], addr);
            }
            #pragma unroll
            for (int mt = 0; mt < 4; mt++)
                #pragma unroll
                for (int nt = 0; nt < 8; nt++)
                    mma_tf32(acc[mt][nt], af[mt][0], af[mt][1], af[mt][2], af[mt][3],
                             bf[nt][0], bf[nt][1]);
        }
        CP_WAIT(STAGES - 2);
        __syncthreads();
    }

    // --- epilogue: float2 stores ---
    #pragma unroll
    for (int mt = 0; mt < 4; mt++) {
        int rg = m0 + warp_m * 64 + mt * 16 + fr;
        #pragma unroll
        for (int nt = 0; nt < 8; nt++) {
            int cg = n0 + warp_n * 64 + nt * 8 + fc * 2;
            float2* p0 = reinterpret_cast<float2*>(out + (size_t)rg * Cq + cg);
            float2* p1 = reinterpret_cast<float2*>(out + (size_t)(rg + 8) * Cq + cg);
            *p0 = make_float2(acc[mt][nt][0], acc[mt][nt][1]);
            *p1 = make_float2(acc[mt][nt][2], acc[mt][nt][3]);
        }
    }
}

// ---------------------------------------------------------------------------
// Host launcher
// ---------------------------------------------------------------------------
extern "C" void kernel_launch(void* const* d_in, const int* in_sizes, int n_in,
                              void* d_out, int out_size)
{
    const float* x   = (const float*)d_in[0];
    const float* mod = (const float*)d_in[1];
    const float* W   = (const float*)d_in[2];
    float* out = (float*)d_out;

    float* yptr = nullptr;
    float* wptr = nullptr;
    cudaGetSymbolAddress((void**)&yptr, g_y);
    cudaGetSymbolAddress((void**)&wptr, g_w);

    cvt_w_kernel<<<(Cq * Dq / 4) / 256, 256>>>(W, wptr);
    softmax_scale_kernel<<<Bq, 256>>>(x, mod, yptr);

    cudaFuncSetAttribute(gemm_tf32_kernel,
                         cudaFuncAttributeMaxDynamicSharedMemorySize, SMEM_BYTES);
    dim3 grid(Cq / BN, Bq / BM);   // (16, 64)
    gemm_tf32_kernel<<<grid, 256, SMEM_BYTES>>>(yptr, wptr, out);
}

// round 6
// speedup vs baseline: 1.9946x; 1.8218x over previous
#include <cuda_runtime.h>
#include <cuda_fp16.h>
#include <cstdint>

// ============================================================================
// out[b,c] = sum_d W[c,d] * (softmax(mod[b,:])[d] + 1) * x[b,d]
// B=8192, D=1024, C=4096, fp32.
// sm_103 baseline PTX only. fp16 mma.sync m16n8k16 + cp.async + ldmatrix.x4.
//   Phase 0: W -> fp16 (g_w)
//   Phase 1: y = (softmax+1)*x -> fp16 (g_y)
//   Phase 2: out = y @ W^T, CTA 128x256, 512 thr (16 warps, 64x32 each),
//            BK=64, 3-stage cp.async pipeline.
// ============================================================================

#define Bq 8192
#define Dq 1024
#define Cq 4096

#define BM 128
#define BN 256
#define BK 64
#define NT (Dq / BK)        // 16 k-tiles
#define STAGES 3
#define LDH 72              // BK + 8 pad halfs: 144B row stride, conflict-free

#define A_TILE_HALFS (BM * LDH)             // 9216
#define B_TILE_HALFS (BN * LDH)             // 18432
#define STAGE_BYTES ((A_TILE_HALFS + B_TILE_HALFS) * 2)   // 55296
#define SMEM_BYTES (STAGES * STAGE_BYTES)   // 165888

__device__ __half g_y[(size_t)Bq * Dq];
__device__ __half g_w[(size_t)Cq * Dq];

__device__ __forceinline__ uint32_t smem_u32(const void* p) {
    uint32_t a;
    asm("{ .reg .u64 t; cvta.to.shared.u64 t, %1; cvt.u32.u64 %0, t; }" : "=r"(a) : "l"(p));
    return a;
}

__device__ __forceinline__ void cp_async16(uint32_t dst, const void* src) {
    asm volatile("cp.async.cg.shared.global [%0], [%1], 16;" :: "r"(dst), "l"(src) : "memory");
}
#define CP_COMMIT() asm volatile("cp.async.commit_group;" ::: "memory")
#define CP_WAIT(n)  asm volatile("cp.async.wait_group %0;" :: "n"(n) : "memory")

#define LDM_X4(r0, r1, r2, r3, addr) \
    asm volatile("ldmatrix.sync.aligned.m8n8.x4.shared.b16 {%0,%1,%2,%3}, [%4];" \
                 : "=r"(r0), "=r"(r1), "=r"(r2), "=r"(r3) : "r"(addr))

__device__ __forceinline__ void mma_fp16(float c[4], uint32_t a0, uint32_t a1,
                                         uint32_t a2, uint32_t a3,
                                         uint32_t b0, uint32_t b1) {
    asm volatile(
        "mma.sync.aligned.m16n8k16.row.col.f32.f16.f16.f32 "
        "{%0,%1,%2,%3}, {%4,%5,%6,%7}, {%8,%9}, {%0,%1,%2,%3};"
        : "+f"(c[0]), "+f"(c[1]), "+f"(c[2]), "+f"(c[3])
        : "r"(a0), "r"(a1), "r"(a2), "r"(a3), "r"(b0), "r"(b1));
}

// ---------------------------------------------------------------------------
// Phase 0: W (fp32) -> fp16 copy
// ---------------------------------------------------------------------------
__global__ __launch_bounds__(256) void cvt_w_kernel(const float* __restrict__ W,
                                                    __half* __restrict__ Wt)
{
    size_t i = (size_t)blockIdx.x * 256 + threadIdx.x;
    float4 v = reinterpret_cast<const float4*>(W)[i];
    __half2 h0 = __floats2half2_rn(v.x, v.y);
    __half2 h1 = __floats2half2_rn(v.z, v.w);
    reinterpret_cast<uint2*>(Wt)[i] = make_uint2(
        *reinterpret_cast<uint32_t*>(&h0), *reinterpret_cast<uint32_t*>(&h1));
}

// ---------------------------------------------------------------------------
// Phase 1: y[b,d] = (softmax(mod[b,:])[d] + 1) * x[b,d], fp16
// ---------------------------------------------------------------------------
__global__ __launch_bounds__(256) void softmax_scale_kernel(
    const float* __restrict__ x, const float* __restrict__ mod, __half* __restrict__ y)
{
    int b = blockIdx.x;
    int t = threadIdx.x;
    const float4 m4 = reinterpret_cast<const float4*>(mod + (size_t)b * Dq)[t];
    const float4 x4 = reinterpret_cast<const float4*>(x + (size_t)b * Dq)[t];

    float mx = fmaxf(fmaxf(m4.x, m4.y), fmaxf(m4.z, m4.w));
    #pragma unroll
    for (int o = 16; o; o >>= 1) mx = fmaxf(mx, __shfl_xor_sync(0xffffffffu, mx, o));

    __shared__ float sred[8];
    int w = t >> 5, l = t & 31;
    if (l == 0) sred[w] = mx;
    __syncthreads();
    float gmx = sred[0];
    #pragma unroll
    for (int i = 1; i < 8; i++) gmx = fmaxf(gmx, sred[i]);
    __syncthreads();

    float e0 = expf(m4.x - gmx), e1 = expf(m4.y - gmx);
    float e2 = expf(m4.z - gmx), e3 = expf(m4.w - gmx);
    float s = e0 + e1 + e2 + e3;
    #pragma unroll
    for (int o = 16; o; o >>= 1) s += __shfl_xor_sync(0xffffffffu, s, o);
    if (l == 0) sred[w] = s;
    __syncthreads();
    float tot = 0.0f;
    #pragma unroll
    for (int i = 0; i < 8; i++) tot += sred[i];
    float inv = 1.0f / tot;

    __half2 h0 = __floats2half2_rn(fmaf(e0, inv, 1.0f) * x4.x,
                                   fmaf(e1, inv, 1.0f) * x4.y);
    __half2 h1 = __floats2half2_rn(fmaf(e2, inv, 1.0f) * x4.z,
                                   fmaf(e3, inv, 1.0f) * x4.w);
    reinterpret_cast<uint2*>(y + (size_t)b * Dq)[t] = make_uint2(
        *reinterpret_cast<uint32_t*>(&h0), *reinterpret_cast<uint32_t*>(&h1));
}

// ---------------------------------------------------------------------------
// Phase 2: out = y @ W^T. CTA tile 128(M) x 256(N) x 64(K), 512 threads,
// 16 warps in 2(m) x 8(n); warp tile 64x32. fp16 m16n8k16.
// ---------------------------------------------------------------------------
__global__ __launch_bounds__(512, 1) void gemm_fp16_kernel(
    const __half* __restrict__ A,   // g_y  [B][D]
    const __half* __restrict__ Bw,  // g_w  [C][D]
    float* __restrict__ out)        // [B][C]
{
    extern __shared__ __half smem[];
    const uint32_t sbase = smem_u32(smem);
    const int tid  = threadIdx.x;
    const int wid  = tid >> 5;
    const int lane = tid & 31;
    const int m0 = blockIdx.y * BM;
    const int n0 = blockIdx.x * BN;
    const int warp_m = wid >> 3;   // 0..1 -> 64-row half of M
    const int warp_n = wid & 7;    // 0..7 -> 32-col slice of N

    // --- async tile loader: 512 threads, 16B chunks; rows of 64 fp16 = 128B
    const int ldrow = tid >> 3;       // 0..63
    const int ldch  = (tid & 7) * 8;  // fp16 offset of 16B chunk
    auto load_tile = [&](int s, int kt) {
        const int k0 = kt * BK;
        const uint32_t sA = sbase + (uint32_t)(s * STAGE_BYTES);
        const uint32_t sB = sA + A_TILE_HALFS * 2u;
        #pragma unroll
        for (int i = 0; i < 2; i++) {
            int r = ldrow + 64 * i;
            cp_async16(sA + (uint32_t)(r * LDH + ldch) * 2u,
                       A + (size_t)(m0 + r) * Dq + k0 + ldch);
        }
        #pragma unroll
        for (int i = 0; i < 4; i++) {
            int r = ldrow + 64 * i;
            cp_async16(sB + (uint32_t)(r * LDH + ldch) * 2u,
                       Bw + (size_t)(n0 + r) * Dq + k0 + ldch);
        }
    };

    float acc[4][4][4];
    #pragma unroll
    for (int mt = 0; mt < 4; mt++)
        #pragma unroll
        for (int nt = 0; nt < 4; nt++)
            #pragma unroll
            for (int i = 0; i < 4; i++) acc[mt][nt][i] = 0.0f;

    int fetch = 0;
    #pragma unroll
    for (; fetch < STAGES - 1; fetch++) { load_tile(fetch, fetch); CP_COMMIT(); }
    CP_WAIT(STAGES - 2);
    __syncthreads();

    // ldmatrix lane addressing: lanes 0-15 -> 16 rows at k-offset 0,
    // lanes 16-31 -> same rows at k-offset 8 halfs (16B)
    const int lrow = lane & 15;
    const int kh   = (lane >> 4) * 8;
    const uint32_t offA0 = (uint32_t)((warp_m * 64 + lrow) * LDH + kh);
    const uint32_t offB0 = (uint32_t)((warp_n * 32 + lrow) * LDH + kh);

    const int fr = lane >> 2;      // c-frag row
    const int fc = lane & 3;       // c-frag col pair

    for (int kt = 0; kt < NT; kt++) {
        const int cur = kt % STAGES;
        if (fetch < NT) { load_tile(fetch % STAGES, fetch); fetch++; }
        CP_COMMIT();

        const uint32_t sA = sbase + (uint32_t)(cur * STAGE_BYTES);
        const uint32_t sB = sA + A_TILE_HALFS * 2u;

        #pragma unroll
        for (int ks = 0; ks < 4; ks++) {     // 4 x k16 per 64-elem ktile
            uint32_t af[4][4];
            uint32_t bf[4][2];
            #pragma unroll
            for (int mt = 0; mt < 4; mt++) {
                uint32_t addr = sA + (offA0 + (uint32_t)(mt * 16 * LDH + ks * 16)) * 2u;
                LDM_X4(af[mt][0], af[mt][1], af[mt][2], af[mt][3], addr);
            }
            #pragma unroll
            for (int np = 0; np < 2; np++) { // covers nt = 2*np, 2*np+1
                uint32_t addr = sB + (offB0 + (uint32_t)(np * 16 * LDH + ks * 16)) * 2u;
                LDM_X4(bf[2 * np][0], bf[2 * np + 1][0],
                       bf[2 * np][1], bf[2 * np + 1][1], addr);
            }
            #pragma unroll
            for (int mt = 0; mt < 4; mt++)
                #pragma unroll
                for (int nt = 0; nt < 4; nt++)
                    mma_fp16(acc[mt][nt], af[mt][0], af[mt][1], af[mt][2], af[mt][3],
                             bf[nt][0], bf[nt][1]);
        }
        CP_WAIT(STAGES - 2);
        __syncthreads();
    }

    // --- epilogue: float2 stores ---
    #pragma unroll
    for (int mt = 0; mt < 4; mt++) {
        int rg = m0 + warp_m * 64 + mt * 16 + fr;
        #pragma unroll
        for (int nt = 0; nt < 4; nt++) {
            int cg = n0 + warp_n * 32 + nt * 8 + fc * 2;
            float2* p0 = reinterpret_cast<float2*>(out + (size_t)rg * Cq + cg);
            float2* p1 = reinterpret_cast<float2*>(out + (size_t)(rg + 8) * Cq + cg);
            *p0 = make_float2(acc[mt][nt][0], acc[mt][nt][1]);
            *p1 = make_float2(acc[mt][nt][2], acc[mt][nt][3]);
        }
    }
}

// ---------------------------------------------------------------------------
// Host launcher
// ---------------------------------------------------------------------------
extern "C" void kernel_launch(void* const* d_in, const int* in_sizes, int n_in,
                              void* d_out, int out_size)
{
    const float* x   = (const float*)d_in[0];
    const float* mod = (const float*)d_in[1];
    const float* W   = (const float*)d_in[2];
    float* out = (float*)d_out;

    __half* yptr = nullptr;
    __half* wptr = nullptr;
    cudaGetSymbolAddress((void**)&yptr, g_y);
    cudaGetSymbolAddress((void**)&wptr, g_w);

    cvt_w_kernel<<<(Cq * Dq / 4) / 256, 256>>>(W, wptr);
    softmax_scale_kernel<<<Bq, 256>>>(x, mod, yptr);

    cudaFuncSetAttribute(gemm_fp16_kernel,
                         cudaFuncAttributeMaxDynamicSharedMemorySize, SMEM_BYTES);
    dim3 grid(Cq / BN, Bq / BM);   // (16, 64)
    gemm_fp16_kernel<<<grid, 512, SMEM_BYTES>>>(yptr, wptr, out);
}

// round 7
// speedup vs baseline: 2.0472x; 1.0264x over previous
#include <cuda_runtime.h>
#include <cuda_fp16.h>
#include <cstdint>

// ============================================================================
// out[b,c] = sum_d W[c,d] * (softmax(mod[b,:])[d] + 1) * x[b,d]
// B=8192, D=1024, C=4096, fp32.
// sm_103 baseline PTX. fp16 mma.sync m16n8k16 (pipe ceiling ~1024 FLOP/cyc/SM).
//   Phase 0+1 fused: W->fp16 and y=(softmax+1)*x->fp16 in one grid
//   Phase 2: out = y @ W^T, CTA 128x128, 256 thr, 3-stage cp.async, 2 CTA/SM
// ============================================================================

#define Bq 8192
#define Dq 1024
#define Cq 4096

#define BM 128
#define BN 128
#define BK 64
#define NT (Dq / BK)        // 16 k-tiles
#define STAGES 3
#define LDH 72              // BK + 8 pad halfs: 144B row stride, conflict-free

#define A_TILE_HALFS (BM * LDH)             // 9216
#define B_TILE_HALFS (BN * LDH)             // 9216
#define STAGE_BYTES ((A_TILE_HALFS + B_TILE_HALFS) * 2)   // 36864
#define SMEM_BYTES (STAGES * STAGE_BYTES)   // 110592  -> 2 CTAs/SM fits 216KB

#define W_CTAS 1024         // W cvt: 4M floats / (256 thr * 16 floats)

__device__ __half g_y[(size_t)Bq * Dq];
__device__ __half g_w[(size_t)Cq * Dq];

__device__ __forceinline__ uint32_t smem_u32(const void* p) {
    uint32_t a;
    asm("{ .reg .u64 t; cvta.to.shared.u64 t, %1; cvt.u32.u64 %0, t; }" : "=r"(a) : "l"(p));
    return a;
}

__device__ __forceinline__ void cp_async16(uint32_t dst, const void* src) {
    asm volatile("cp.async.cg.shared.global [%0], [%1], 16;" :: "r"(dst), "l"(src) : "memory");
}
#define CP_COMMIT() asm volatile("cp.async.commit_group;" ::: "memory")
#define CP_WAIT(n)  asm volatile("cp.async.wait_group %0;" :: "n"(n) : "memory")

#define LDM_X4(r0, r1, r2, r3, addr) \
    asm volatile("ldmatrix.sync.aligned.m8n8.x4.shared.b16 {%0,%1,%2,%3}, [%4];" \
                 : "=r"(r0), "=r"(r1), "=r"(r2), "=r"(r3) : "r"(addr))

__device__ __forceinline__ void mma_fp16(float c[4], uint32_t a0, uint32_t a1,
                                         uint32_t a2, uint32_t a3,
                                         uint32_t b0, uint32_t b1) {
    asm volatile(
        "mma.sync.aligned.m16n8k16.row.col.f32.f16.f16.f32 "
        "{%0,%1,%2,%3}, {%4,%5,%6,%7}, {%8,%9}, {%0,%1,%2,%3};"
        : "+f"(c[0]), "+f"(c[1]), "+f"(c[2]), "+f"(c[3])
        : "r"(a0), "r"(a1), "r"(a2), "r"(a3), "r"(b0), "r"(b1));
}

// ---------------------------------------------------------------------------
// Fused prologue: CTAs [0, Bq) do softmax rows; CTAs [Bq, Bq+W_CTAS) cvt W.
// ---------------------------------------------------------------------------
__global__ __launch_bounds__(256) void prologue_kernel(
    const float* __restrict__ x, const float* __restrict__ mod,
    const float* __restrict__ W,
    __half* __restrict__ y, __half* __restrict__ w16)
{
    const int t = threadIdx.x;
    if (blockIdx.x >= Bq) {
        // ---- W -> fp16, 16 floats (4x float4) per thread, MLP=4 ----
        size_t base = (size_t)(blockIdx.x - Bq) * (256 * 4) + t;
        const float4* src = reinterpret_cast<const float4*>(W);
        uint2* dst = reinterpret_cast<uint2*>(w16);
        float4 v0 = src[base];
        float4 v1 = src[base + 256];
        float4 v2 = src[base + 512];
        float4 v3 = src[base + 768];
        #pragma unroll
        for (int i = 0; i < 4; i++) {
            float4 v = (i == 0) ? v0 : (i == 1) ? v1 : (i == 2) ? v2 : v3;
            __half2 h0 = __floats2half2_rn(v.x, v.y);
            __half2 h1 = __floats2half2_rn(v.z, v.w);
            dst[base + i * 256] = make_uint2(*reinterpret_cast<uint32_t*>(&h0),
                                             *reinterpret_cast<uint32_t*>(&h1));
        }
        return;
    }

    // ---- softmax row ----
    const int b = blockIdx.x;
    const float4 m4 = reinterpret_cast<const float4*>(mod + (size_t)b * Dq)[t];
    const float4 x4 = reinterpret_cast<const float4*>(x + (size_t)b * Dq)[t];

    float mx = fmaxf(fmaxf(m4.x, m4.y), fmaxf(m4.z, m4.w));
    #pragma unroll
    for (int o = 16; o; o >>= 1) mx = fmaxf(mx, __shfl_xor_sync(0xffffffffu, mx, o));

    __shared__ float sred[8];
    int w = t >> 5, l = t & 31;
    if (l == 0) sred[w] = mx;
    __syncthreads();
    float gmx = sred[0];
    #pragma unroll
    for (int i = 1; i < 8; i++) gmx = fmaxf(gmx, sred[i]);
    __syncthreads();

    float e0 = expf(m4.x - gmx), e1 = expf(m4.y - gmx);
    float e2 = expf(m4.z - gmx), e3 = expf(m4.w - gmx);
    float s = e0 + e1 + e2 + e3;
    #pragma unroll
    for (int o = 16; o; o >>= 1) s += __shfl_xor_sync(0xffffffffu, s, o);
    if (l == 0) sred[w] = s;
    __syncthreads();
    float tot = 0.0f;
    #pragma unroll
    for (int i = 0; i < 8; i++) tot += sred[i];
    float inv = 1.0f / tot;

    __half2 h0 = __floats2half2_rn(fmaf(e0, inv, 1.0f) * x4.x,
                                   fmaf(e1, inv, 1.0f) * x4.y);
    __half2 h1 = __floats2half2_rn(fmaf(e2, inv, 1.0f) * x4.z,
                                   fmaf(e3, inv, 1.0f) * x4.w);
    reinterpret_cast<uint2*>(y + (size_t)b * Dq)[t] = make_uint2(
        *reinterpret_cast<uint32_t*>(&h0), *reinterpret_cast<uint32_t*>(&h1));
}

// ---------------------------------------------------------------------------
// GEMM: out = y @ W^T. CTA 128x128x64, 256 threads (8 warps, 2m x 4n,
// warp tile 64x32), 3-stage cp.async, 2 CTAs/SM.
// ---------------------------------------------------------------------------
__global__ __launch_bounds__(256, 2) void gemm_fp16_kernel(
    const __half* __restrict__ A,   // g_y  [B][D]
    const __half* __restrict__ Bw,  // g_w  [C][D]
    float* __restrict__ out)        // [B][C]
{
    extern __shared__ __half smem[];
    const uint32_t sbase = smem_u32(smem);
    const int tid  = threadIdx.x;
    const int wid  = tid >> 5;
    const int lane = tid & 31;
    const int m0 = blockIdx.y * BM;
    const int n0 = blockIdx.x * BN;
    const int warp_m = wid >> 2;   // 0..1
    const int warp_n = wid & 3;    // 0..3

    const int ldrow = tid >> 3;       // 0..31
    const int ldch  = (tid & 7) * 8;  // fp16 offset of 16B chunk
    auto load_tile = [&](int s, int kt) {
        const int k0 = kt * BK;
        const uint32_t sA = sbase + (uint32_t)(s * STAGE_BYTES);
        const uint32_t sB = sA + A_TILE_HALFS * 2u;
        #pragma unroll
        for (int i = 0; i < 4; i++) {
            int r = ldrow + 32 * i;
            cp_async16(sA + (uint32_t)(r * LDH + ldch) * 2u,
                       A + (size_t)(m0 + r) * Dq + k0 + ldch);
        }
        #pragma unroll
        for (int i = 0; i < 4; i++) {
            int r = ldrow + 32 * i;
            cp_async16(sB + (uint32_t)(r * LDH + ldch) * 2u,
                       Bw + (size_t)(n0 + r) * Dq + k0 + ldch);
        }
    };

    float acc[4][4][4];
    #pragma unroll
    for (int mt = 0; mt < 4; mt++)
        #pragma unroll
        for (int nt = 0; nt < 4; nt++)
            #pragma unroll
            for (int i = 0; i < 4; i++) acc[mt][nt][i] = 0.0f;

    int fetch = 0;
    #pragma unroll
    for (; fetch < STAGES - 1; fetch++) { load_tile(fetch, fetch); CP_COMMIT(); }
    CP_WAIT(STAGES - 2);
    __syncthreads();

    const int lrow = lane & 15;
    const int kh   = (lane >> 4) * 8;
    const uint32_t offA0 = (uint32_t)((warp_m * 64 + lrow) * LDH + kh);
    const uint32_t offB0 = (uint32_t)((warp_n * 32 + lrow) * LDH + kh);

    const int fr = lane >> 2;
    const int fc = lane & 3;

    for (int kt = 0; kt < NT; kt++) {
        const int cur = kt % STAGES;
        if (fetch < NT) { load_tile(fetch % STAGES, fetch); fetch++; }
        CP_COMMIT();

        const uint32_t sA = sbase + (uint32_t)(cur * STAGE_BYTES);
        const uint32_t sB = sA + A_TILE_HALFS * 2u;

        #pragma unroll
        for (int ks = 0; ks < 4; ks++) {
            uint32_t af[4][4];
            uint32_t bf[4][2];
            #pragma unroll
            for (int mt = 0; mt < 4; mt++) {
                uint32_t addr = sA + (offA0 + (uint32_t)(mt * 16 * LDH + ks * 16)) * 2u;
                LDM_X4(af[mt][0], af[mt][1], af[mt][2], af[mt][3], addr);
            }
            #pragma unroll
            for (int np = 0; np < 2; np++) {
                uint32_t addr = sB + (offB0 + (uint32_t)(np * 16 * LDH + ks * 16)) * 2u;
                LDM_X4(bf[2 * np][0], bf[2 * np + 1][0],
                       bf[2 * np][1], bf[2 * np + 1][1], addr);
            }
            #pragma unroll
            for (int mt = 0; mt < 4; mt++)
                #pragma unroll
                for (int nt = 0; nt < 4; nt++)
                    mma_fp16(acc[mt][nt], af[mt][0], af[mt][1], af[mt][2], af[mt][3],
                             bf[nt][0], bf[nt][1]);
        }
        CP_WAIT(STAGES - 2);
        __syncthreads();
    }

    // --- epilogue: float2 stores ---
    #pragma unroll
    for (int mt = 0; mt < 4; mt++) {
        int rg = m0 + warp_m * 64 + mt * 16 + fr;
        #pragma unroll
        for (int nt = 0; nt < 4; nt++) {
            int cg = n0 + warp_n * 32 + nt * 8 + fc * 2;
            float2* p0 = reinterpret_cast<float2*>(out + (size_t)rg * Cq + cg);
            float2* p1 = reinterpret_cast<float2*>(out + (size_t)(rg + 8) * Cq + cg);
            *p0 = make_float2(acc[mt][nt][0], acc[mt][nt][1]);
            *p1 = make_float2(acc[mt][nt][2], acc[mt][nt][3]);
        }
    }
}

// ---------------------------------------------------------------------------
// Host launcher
// ---------------------------------------------------------------------------
extern "C" void kernel_launch(void* const* d_in, const int* in_sizes, int n_in,
                              void* d_out, int out_size)
{
    const float* x   = (const float*)d_in[0];
    const float* mod = (const float*)d_in[1];
    const float* W   = (const float*)d_in[2];
    float* out = (float*)d_out;

    __half* yptr = nullptr;
    __half* wptr = nullptr;
    cudaGetSymbolAddress((void**)&yptr, g_y);
    cudaGetSymbolAddress((void**)&wptr, g_w);

    prologue_kernel<<<Bq + W_CTAS, 256>>>(x, mod, W, yptr, wptr);

    cudaFuncSetAttribute(gemm_fp16_kernel,
                         cudaFuncAttributeMaxDynamicSharedMemorySize, SMEM_BYTES);
    dim3 grid(Cq / BN, Bq / BM);   // (32, 64) = 2048 CTAs
    gemm_fp16_kernel<<<grid, 256, SMEM_BYTES>>>(yptr, wptr, out);
}

// round 8
// speedup vs baseline: 2.5741x; 1.2574x over previous
#include <cuda_runtime.h>
#include <cuda_fp16.h>
#include <cstdint>

// ============================================================================
// out[b,c] = sum_d W[c,d] * (softmax(mod[b,:])[d] + 1) * x[b,d]
// B=8192, D=1024, C=4096, fp32.
// fp16 mma.sync m16n8k16. Profile R6: tensor=50%, smem crossbar co-binding.
// R7: CTA 128x256, 8 warps (64x64 each), fragment double-buffering across ks,
//     4-stage cp.async, 1 CTA/SM.
// ============================================================================

#define Bq 8192
#define Dq 1024
#define Cq 4096

#define BM 128
#define BN 256
#define BK 64
#define NT (Dq / BK)        // 16 k-tiles
#define STAGES 4
#define LDH 72              // BK + 8 pad halfs: 144B row stride, conflict-free

#define A_TILE_HALFS (BM * LDH)             // 9216
#define B_TILE_HALFS (BN * LDH)             // 18432
#define STAGE_BYTES ((A_TILE_HALFS + B_TILE_HALFS) * 2)   // 55296
#define SMEM_BYTES (STAGES * STAGE_BYTES)   // 221184

#define W_CTAS 1024

__device__ __half g_y[(size_t)Bq * Dq];
__device__ __half g_w[(size_t)Cq * Dq];

__device__ __forceinline__ uint32_t smem_u32(const void* p) {
    uint32_t a;
    asm("{ .reg .u64 t; cvta.to.shared.u64 t, %1; cvt.u32.u64 %0, t; }" : "=r"(a) : "l"(p));
    return a;
}

__device__ __forceinline__ void cp_async16(uint32_t dst, const void* src) {
    asm volatile("cp.async.cg.shared.global [%0], [%1], 16;" :: "r"(dst), "l"(src) : "memory");
}
#define CP_COMMIT() asm volatile("cp.async.commit_group;" ::: "memory")
#define CP_WAIT(n)  asm volatile("cp.async.wait_group %0;" :: "n"(n) : "memory")

#define LDM_X4(r0, r1, r2, r3, addr) \
    asm volatile("ldmatrix.sync.aligned.m8n8.x4.shared.b16 {%0,%1,%2,%3}, [%4];" \
                 : "=r"(r0), "=r"(r1), "=r"(r2), "=r"(r3) : "r"(addr))

__device__ __forceinline__ void mma_fp16(float c[4], uint32_t a0, uint32_t a1,
                                         uint32_t a2, uint32_t a3,
                                         uint32_t b0, uint32_t b1) {
    asm volatile(
        "mma.sync.aligned.m16n8k16.row.col.f32.f16.f16.f32 "
        "{%0,%1,%2,%3}, {%4,%5,%6,%7}, {%8,%9}, {%0,%1,%2,%3};"
        : "+f"(c[0]), "+f"(c[1]), "+f"(c[2]), "+f"(c[3])
        : "r"(a0), "r"(a1), "r"(a2), "r"(a3), "r"(b0), "r"(b1));
}

// ---------------------------------------------------------------------------
// Fused prologue: CTAs [0, Bq) softmax rows; CTAs [Bq, Bq+W_CTAS) cvt W.
// ---------------------------------------------------------------------------
__global__ __launch_bounds__(256) void prologue_kernel(
    const float* __restrict__ x, const float* __restrict__ mod,
    const float* __restrict__ W,
    __half* __restrict__ y, __half* __restrict__ w16)
{
    const int t = threadIdx.x;
    if (blockIdx.x >= Bq) {
        size_t base = (size_t)(blockIdx.x - Bq) * (256 * 4) + t;
        const float4* src = reinterpret_cast<const float4*>(W);
        uint2* dst = reinterpret_cast<uint2*>(w16);
        float4 v0 = src[base];
        float4 v1 = src[base + 256];
        float4 v2 = src[base + 512];
        float4 v3 = src[base + 768];
        #pragma unroll
        for (int i = 0; i < 4; i++) {
            float4 v = (i == 0) ? v0 : (i == 1) ? v1 : (i == 2) ? v2 : v3;
            __half2 h0 = __floats2half2_rn(v.x, v.y);
            __half2 h1 = __floats2half2_rn(v.z, v.w);
            dst[base + i * 256] = make_uint2(*reinterpret_cast<uint32_t*>(&h0),
                                             *reinterpret_cast<uint32_t*>(&h1));
        }
        return;
    }

    const int b = blockIdx.x;
    const float4 m4 = reinterpret_cast<const float4*>(mod + (size_t)b * Dq)[t];
    const float4 x4 = reinterpret_cast<const float4*>(x + (size_t)b * Dq)[t];

    float mx = fmaxf(fmaxf(m4.x, m4.y), fmaxf(m4.z, m4.w));
    #pragma unroll
    for (int o = 16; o; o >>= 1) mx = fmaxf(mx, __shfl_xor_sync(0xffffffffu, mx, o));

    __shared__ float sred[8];
    int w = t >> 5, l = t & 31;
    if (l == 0) sred[w] = mx;
    __syncthreads();
    float gmx = sred[0];
    #pragma unroll
    for (int i = 1; i < 8; i++) gmx = fmaxf(gmx, sred[i]);
    __syncthreads();

    float e0 = expf(m4.x - gmx), e1 = expf(m4.y - gmx);
    float e2 = expf(m4.z - gmx), e3 = expf(m4.w - gmx);
    float s = e0 + e1 + e2 + e3;
    #pragma unroll
    for (int o = 16; o; o >>= 1) s += __shfl_xor_sync(0xffffffffu, s, o);
    if (l == 0) sred[w] = s;
    __syncthreads();
    float tot = 0.0f;
    #pragma unroll
    for (int i = 0; i < 8; i++) tot += sred[i];
    float inv = 1.0f / tot;

    __half2 h0 = __floats2half2_rn(fmaf(e0, inv, 1.0f) * x4.x,
                                   fmaf(e1, inv, 1.0f) * x4.y);
    __half2 h1 = __floats2half2_rn(fmaf(e2, inv, 1.0f) * x4.z,
                                   fmaf(e3, inv, 1.0f) * x4.w);
    reinterpret_cast<uint2*>(y + (size_t)b * Dq)[t] = make_uint2(
        *reinterpret_cast<uint32_t*>(&h0), *reinterpret_cast<uint32_t*>(&h1));
}

// ---------------------------------------------------------------------------
// GEMM: out = y @ W^T. CTA 128(M) x 256(N) x 64(K), 256 threads,
// 8 warps 2(m) x 4(n), warp tile 64x64. ks-level fragment double-buffering.
// ---------------------------------------------------------------------------
__global__ __launch_bounds__(256, 1) void gemm_fp16_kernel(
    const __half* __restrict__ A,   // g_y  [B][D]
    const __half* __restrict__ Bw,  // g_w  [C][D]
    float* __restrict__ out)        // [B][C]
{
    extern __shared__ __half smem[];
    const uint32_t sbase = smem_u32(smem);
    const int tid  = threadIdx.x;
    const int wid  = tid >> 5;
    const int lane = tid & 31;
    const int m0 = blockIdx.y * BM;
    const int n0 = blockIdx.x * BN;
    const int warp_m = wid >> 2;   // 0..1 -> 64-row half of M
    const int warp_n = wid & 3;    // 0..3 -> 64-col quarter of N

    // --- async tile loader: 256 thr, 16B chunks ---
    const int ldrow = tid >> 3;       // 0..31
    const int ldch  = (tid & 7) * 8;  // half-offset of 16B chunk
    auto load_tile = [&](int s, int kt) {
        const int k0 = kt * BK;
        const uint32_t sA = sbase + (uint32_t)(s * STAGE_BYTES);
        const uint32_t sB = sA + A_TILE_HALFS * 2u;
        #pragma unroll
        for (int i = 0; i < 4; i++) {
            int r = ldrow + 32 * i;
            cp_async16(sA + (uint32_t)(r * LDH + ldch) * 2u,
                       A + (size_t)(m0 + r) * Dq + k0 + ldch);
        }
        #pragma unroll
        for (int i = 0; i < 8; i++) {
            int r = ldrow + 32 * i;
            cp_async16(sB + (uint32_t)(r * LDH + ldch) * 2u,
                       Bw + (size_t)(n0 + r) * Dq + k0 + ldch);
        }
    };

    float acc[4][8][4];
    #pragma unroll
    for (int mt = 0; mt < 4; mt++)
        #pragma unroll
        for (int nt = 0; nt < 8; nt++)
            #pragma unroll
            for (int i = 0; i < 4; i++) acc[mt][nt][i] = 0.0f;

    int fetch = 0;
    #pragma unroll
    for (; fetch < STAGES - 1; fetch++) { load_tile(fetch, fetch); CP_COMMIT(); }
    CP_WAIT(STAGES - 2);
    __syncthreads();

    // ldmatrix lane addressing
    const int lrow = lane & 15;
    const int kh   = (lane >> 4) * 8;
    const uint32_t offA0 = (uint32_t)((warp_m * 64 + lrow) * LDH + kh);
    const uint32_t offB0 = (uint32_t)((warp_n * 64 + lrow) * LDH + kh);

    const int fr = lane >> 2;
    const int fc = lane & 3;

    // fragment double buffers
    uint32_t af[2][4][4];
    uint32_t bf[2][8][2];

    auto load_frags = [&](int buf, uint32_t sA, uint32_t sB, int ks) {
        #pragma unroll
        for (int mt = 0; mt < 4; mt++) {
            uint32_t addr = sA + (offA0 + (uint32_t)(mt * 16 * LDH + ks * 16)) * 2u;
            LDM_X4(af[buf][mt][0], af[buf][mt][1], af[buf][mt][2], af[buf][mt][3], addr);
        }
        #pragma unroll
        for (int np = 0; np < 4; np++) {
            uint32_t addr = sB + (offB0 + (uint32_t)(np * 16 * LDH + ks * 16)) * 2u;
            LDM_X4(bf[buf][2 * np][0], bf[buf][2 * np + 1][0],
                   bf[buf][2 * np][1], bf[buf][2 * np + 1][1], addr);
        }
    };

    {
        const uint32_t sA0 = sbase;
        const uint32_t sB0 = sA0 + A_TILE_HALFS * 2u;
        load_frags(0, sA0, sB0, 0);
    }

    for (int kt = 0; kt < NT; kt++) {
        const int cur = kt % STAGES;
        if (fetch < NT) { load_tile(fetch % STAGES, fetch); fetch++; CP_COMMIT(); }

        const uint32_t sA = sbase + (uint32_t)(cur * STAGE_BYTES);
        const uint32_t sB = sA + A_TILE_HALFS * 2u;

        #pragma unroll
        for (int ks = 0; ks < 4; ks++) {
            const int buf = ks & 1;
            if (ks < 3) load_frags(buf ^ 1, sA, sB, ks + 1);
            #pragma unroll
            for (int mt = 0; mt < 4; mt++)
                #pragma unroll
                for (int nt = 0; nt < 8; nt++)
                    mma_fp16(acc[mt][nt],
                             af[buf][mt][0], af[buf][mt][1], af[buf][mt][2], af[buf][mt][3],
                             bf[buf][nt][0], bf[buf][nt][1]);
        }

        // make next tile resident, then preload its ks=0 frags into buf 0
        CP_WAIT(STAGES - 2);
        __syncthreads();
        if (kt + 1 < NT) {
            const uint32_t sAn = sbase + (uint32_t)(((kt + 1) % STAGES) * STAGE_BYTES);
            const uint32_t sBn = sAn + A_TILE_HALFS * 2u;
            load_frags(0, sAn, sBn, 0);
        }
    }

    // --- epilogue: float2 stores ---
    #pragma unroll
    for (int mt = 0; mt < 4; mt++) {
        int rg = m0 + warp_m * 64 + mt * 16 + fr;
        #pragma unroll
        for (int nt = 0; nt < 8; nt++) {
            int cg = n0 + warp_n * 64 + nt * 8 + fc * 2;
            float2* p0 = reinterpret_cast<float2*>(out + (size_t)rg * Cq + cg);
            float2* p1 = reinterpret_cast<float2*>(out + (size_t)(rg + 8) * Cq + cg);
            *p0 = make_float2(acc[mt][nt][0], acc[mt][nt][1]);
            *p1 = make_float2(acc[mt][nt][2], acc[mt][nt][3]);
        }
    }
}

// ---------------------------------------------------------------------------
// Host launcher
// ---------------------------------------------------------------------------
extern "C" void kernel_launch(void* const* d_in, const int* in_sizes, int n_in,
                              void* d_out, int out_size)
{
    const float* x   = (const float*)d_in[0];
    const float* mod = (const float*)d_in[1];
    const float* W   = (const float*)d_in[2];
    float* out = (float*)d_out;

    __half* yptr = nullptr;
    __half* wptr = nullptr;
    cudaGetSymbolAddress((void**)&yptr, g_y);
    cudaGetSymbolAddress((void**)&wptr, g_w);

    prologue_kernel<<<Bq + W_CTAS, 256>>>(x, mod, W, yptr, wptr);

    cudaFuncSetAttribute(gemm_fp16_kernel,
                         cudaFuncAttributeMaxDynamicSharedMemorySize, SMEM_BYTES);
    dim3 grid(Cq / BN, Bq / BM);   // (16, 64) = 1024 CTAs
    gemm_fp16_kernel<<<grid, 256, SMEM_BYTES>>>(yptr, wptr, out);
}